// round 8
// baseline (speedup 1.0000x reference)
#include <cuda_runtime.h>
#include <cuda_bf16.h>

#define NN 100000
#define NE 3200000
#define DF 512
#define HID 16
#define NC 7

// gemm1: 512 rows x 16 cols x 128-k-slice per 256-thread block; thread = 2 rows x 16 cols
#define GROWS 512
#define GKS   128          // k-slice per block (split-K = 4)
#define GKC   16           // k per staged chunk
#define GXST  17           // padded xs row stride (floats)

// ---------------- scratch (no allocations allowed) ----------------
__device__ float g_deg[NN];
__device__ float g_dinv[NN];
__device__ float g_w[NE];                        // per-edge weight (scat1 -> scat2)
__device__ __align__(16) float g_h1[NN * HID];   // x @ W1 (accumulated via red)
__device__ __align__(16) float g_m1[NN * HID];   // aggregated layer1
__device__ __align__(16) float g_t2[NN * 8];     // relu(m1+b1) @ W2, padded to 8
__device__ __align__(16) float g_m2[NN * 8];     // aggregated layer2, padded

// 128-bit global float reduction (sm_90+)
__device__ __forceinline__ void red_add_v4(float* p, float4 v) {
    asm volatile(
        "{\n\t"
        ".reg .u64 pg;\n\t"
        "cvta.to.global.u64 pg, %0;\n\t"
        "red.global.add.v4.f32 [pg], {%1,%2,%3,%4};\n\t"
        "}"
        :: "l"(p), "f"(v.x), "f"(v.y), "f"(v.z), "f"(v.w)
        : "memory");
}

__device__ __forceinline__ void ffma2(unsigned long long& acc,
                                      unsigned long long a, unsigned long long b) {
    asm("fma.rn.f32x2 %0, %1, %2, %0;" : "+l"(acc) : "l"(a), "l"(b));
}

// ---------------- K0: init accumulators ----------------
__global__ void k_init() {
    int i = blockIdx.x * blockDim.x + threadIdx.x;
    if (i < NN) g_deg[i] = 1.0f;          // self-loop contributes 1 to degree
    if (i < NN * HID) { g_m1[i] = 0.0f; g_h1[i] = 0.0f; }
    if (i < NN * 8) g_m2[i] = 0.0f;
}

// ---------------- K1: in-degree ----------------
__global__ void k_deg(const int* __restrict__ ei) {
    int e = blockIdx.x * blockDim.x + threadIdx.x;
    if (e < NE) atomicAdd(&g_deg[ei[NE + e]], 1.0f);
}

// ---------------- K2: dinv ----------------
__global__ void k_dinv() {
    int i = blockIdx.x * blockDim.x + threadIdx.x;
    if (i < NN) g_dinv[i] = rsqrtf(g_deg[i]);   // deg >= 1 always
}

// ---------------- K3: h1 += x @ W1 (split-K, col-pair f32x2, LDS.128 W) -----
__global__ __launch_bounds__(256) void k_gemm1(const float* __restrict__ x,
                                               const float* __restrict__ W1) {
    __shared__ float xs[GROWS * GXST];              // 34.8 KB
    __shared__ __align__(16) float2 Wp[GKS][8];     // 8 KB (col pairs)

    int t = threadIdx.x;
    int rb = blockIdx.x >> 2;
    int ks = (blockIdx.x & 3) * GKS;
    int row0 = rb * GROWS;

    // stage W slice as col-pairs (coalesced float2 loads)
    const float2* W2p = (const float2*)W1;
    #pragma unroll
    for (int i = t; i < GKS * 8; i += 256) {
        int k = i >> 3, c = i & 7;
        Wp[k][c] = W2p[(ks + k) * 8 + c];
    }

    unsigned long long acc[2][8];
    #pragma unroll
    for (int p = 0; p < 2; p++)
        #pragma unroll
        for (int c = 0; c < 8; c++) acc[p][c] = 0ull;

    for (int ch = 0; ch < GKS / GKC; ch++) {
        __syncthreads();
        // stage x chunk: 512 rows x 16 k, row-major padded
        #pragma unroll
        for (int i = 0; i < 8; i++) {
            int lin = t + 256 * i;
            int row = lin >> 2, j = lin & 3;
            int grow = row0 + row;
            float4 v = make_float4(0.f, 0.f, 0.f, 0.f);
            if (grow < NN) v = *(const float4*)&x[grow * DF + ks + ch * GKC + j * 4];
            float* p = &xs[row * GXST + j * 4];
            p[0] = v.x; p[1] = v.y; p[2] = v.z; p[3] = v.w;
        }
        __syncthreads();
        #pragma unroll
        for (int kk = 0; kk < GKC; kk++) {
            int kL = ch * GKC + kk;
            float xa = xs[t * GXST + kk];
            float xb = xs[(t + 256) * GXST + kk];
            unsigned long long xad, xbd;
            asm("mov.b64 %0, {%1,%1};" : "=l"(xad) : "f"(xa));
            asm("mov.b64 %0, {%1,%1};" : "=l"(xbd) : "f"(xb));
            // 4 broadcast LDS.128 (was 8 LDS.64): halves smem phases for W
            ulonglong2 w01 = *(const ulonglong2*)&Wp[kL][0];
            ulonglong2 w23 = *(const ulonglong2*)&Wp[kL][2];
            ulonglong2 w45 = *(const ulonglong2*)&Wp[kL][4];
            ulonglong2 w67 = *(const ulonglong2*)&Wp[kL][6];
            ffma2(acc[0][0], xad, w01.x);  ffma2(acc[1][0], xbd, w01.x);
            ffma2(acc[0][1], xad, w01.y);  ffma2(acc[1][1], xbd, w01.y);
            ffma2(acc[0][2], xad, w23.x);  ffma2(acc[1][2], xbd, w23.x);
            ffma2(acc[0][3], xad, w23.y);  ffma2(acc[1][3], xbd, w23.y);
            ffma2(acc[0][4], xad, w45.x);  ffma2(acc[1][4], xbd, w45.x);
            ffma2(acc[0][5], xad, w45.y);  ffma2(acc[1][5], xbd, w45.y);
            ffma2(acc[0][6], xad, w67.x);  ffma2(acc[1][6], xbd, w67.x);
            ffma2(acc[0][7], xad, w67.y);  ffma2(acc[1][7], xbd, w67.y);
        }
    }

    #pragma unroll
    for (int p = 0; p < 2; p++) {
        int rr = row0 + t + p * 256;
        if (rr < NN) {
            float f[16];
            #pragma unroll
            for (int c = 0; c < 8; c++)
                asm("mov.b64 {%0,%1}, %2;" : "=f"(f[2 * c]), "=f"(f[2 * c + 1]) : "l"(acc[p][c]));
            red_add_v4(&g_h1[rr * HID + 0],  make_float4(f[0],  f[1],  f[2],  f[3]));
            red_add_v4(&g_h1[rr * HID + 4],  make_float4(f[4],  f[5],  f[6],  f[7]));
            red_add_v4(&g_h1[rr * HID + 8],  make_float4(f[8],  f[9],  f[10], f[11]));
            red_add_v4(&g_h1[rr * HID + 12], make_float4(f[12], f[13], f[14], f[15]));
        }
    }
}

// ---------------- K4: layer-1 scatter (4 threads/edge) + w cache -------------
__global__ void k_scat1(const int* __restrict__ ei) {
    int t = blockIdx.x * blockDim.x + threadIdx.x;
    int e = t >> 2, sub = t & 3;
    if (e >= NE) return;
    int src = ei[e];
    int dst = ei[NE + e];
    float w = g_dinv[src] * g_dinv[dst];
    if (sub == 0) g_w[e] = w;
    float4 h = ((const float4*)g_h1)[src * 4 + sub];
    h.x *= w; h.y *= w; h.z *= w; h.w *= w;
    red_add_v4(&g_m1[dst * HID + sub * 4], h);
}

// ---------------- K5: h2 = relu(m1 + selfloop + b1); t2 = h2 @ W2 ------------
__global__ void k_layer2(const float* __restrict__ b1, const float* __restrict__ W2) {
    __shared__ float W2s[HID][8];
    __shared__ float b1s[HID];
    int t = threadIdx.x;
    if (t < HID * NC) W2s[t / NC][t % NC] = W2[t];
    if (t < HID) { W2s[t][7] = 0.0f; b1s[t] = b1[t]; }
    __syncthreads();

    int n = blockIdx.x * blockDim.x + t;
    if (n >= NN) return;
    float dv = g_dinv[n];
    float d2 = dv * dv;

    float h[HID];
    #pragma unroll
    for (int j = 0; j < 4; j++) {
        float4 mv = ((const float4*)g_m1)[n * 4 + j];
        float4 hv = ((const float4*)g_h1)[n * 4 + j];
        h[4 * j + 0] = fmaxf(mv.x + hv.x * d2 + b1s[4 * j + 0], 0.f);
        h[4 * j + 1] = fmaxf(mv.y + hv.y * d2 + b1s[4 * j + 1], 0.f);
        h[4 * j + 2] = fmaxf(mv.z + hv.z * d2 + b1s[4 * j + 2], 0.f);
        h[4 * j + 3] = fmaxf(mv.w + hv.w * d2 + b1s[4 * j + 3], 0.f);
    }

    float o[8];
    #pragma unroll
    for (int c = 0; c < 8; c++) o[c] = 0.f;
    #pragma unroll
    for (int k = 0; k < HID; k++) {
        #pragma unroll
        for (int c = 0; c < 8; c++)
            o[c] += h[k] * W2s[k][c];    // col 7 stays 0
    }
    ((float4*)g_t2)[n * 2 + 0] = make_float4(o[0], o[1], o[2], o[3]);
    ((float4*)g_t2)[n * 2 + 1] = make_float4(o[4], o[5], o[6], o[7]);
}

// ---------------- K6: layer-2 scatter (2 threads/edge, reuses w) -------------
__global__ void k_scat2(const int* __restrict__ ei) {
    int t = blockIdx.x * blockDim.x + threadIdx.x;
    int e = t >> 1, sub = t & 1;
    if (e >= NE) return;
    int src = ei[e];
    int dst = ei[NE + e];
    float w = g_w[e];
    float4 v = ((const float4*)g_t2)[src * 2 + sub];
    v.x *= w; v.y *= w; v.z *= w; v.w *= w;
    red_add_v4(&g_m2[dst * 8 + sub * 4], v);
}

// ---------------- K7: finalize: + selfloop + b2, log_softmax -----------------
__global__ void k_final(const float* __restrict__ b2, float* __restrict__ out) {
    int n = blockIdx.x * blockDim.x + threadIdx.x;
    if (n >= NN) return;
    float dv = g_dinv[n];
    float d2 = dv * dv;

    float4 m0 = ((const float4*)g_m2)[n * 2 + 0];
    float4 m1v = ((const float4*)g_m2)[n * 2 + 1];
    float4 t0 = ((const float4*)g_t2)[n * 2 + 0];
    float4 t1 = ((const float4*)g_t2)[n * 2 + 1];

    float l[NC];
    l[0] = m0.x + t0.x * d2 + b2[0];
    l[1] = m0.y + t0.y * d2 + b2[1];
    l[2] = m0.z + t0.z * d2 + b2[2];
    l[3] = m0.w + t0.w * d2 + b2[3];
    l[4] = m1v.x + t1.x * d2 + b2[4];
    l[5] = m1v.y + t1.y * d2 + b2[5];
    l[6] = m1v.z + t1.z * d2 + b2[6];

    float mx = l[0];
    #pragma unroll
    for (int c = 1; c < NC; c++) mx = fmaxf(mx, l[c]);
    float s = 0.f;
    #pragma unroll
    for (int c = 0; c < NC; c++) s += expf(l[c] - mx);
    float lse = mx + logf(s);
    #pragma unroll
    for (int c = 0; c < NC; c++) out[n * NC + c] = l[c] - lse;
}

// ---------------- launch ----------------
extern "C" void kernel_launch(void* const* d_in, const int* in_sizes, int n_in,
                              void* d_out, int out_size) {
    const float* x   = (const float*)d_in[0];
    const int*   ei  = (const int*)d_in[1];
    const float* W1  = (const float*)d_in[2];
    const float* b1  = (const float*)d_in[3];
    const float* W2  = (const float*)d_in[4];
    const float* b2  = (const float*)d_in[5];
    float*       out = (float*)d_out;

    int gblocks = ((NN + GROWS - 1) / GROWS) * 4;   // 196 * 4 = 784

    k_init<<<(NN * HID + 255) / 256, 256>>>();
    k_deg<<<(NE + 255) / 256, 256>>>(ei);
    k_dinv<<<(NN + 255) / 256, 256>>>();
    k_gemm1<<<gblocks, 256>>>(x, W1);
    k_scat1<<<(NE * 4 + 255) / 256, 256>>>(ei);
    k_layer2<<<(NN + 255) / 256, 256>>>(b1, W2);
    k_scat2<<<(NE * 2 + 255) / 256, 256>>>(ei);
    k_final<<<(NN + 255) / 256, 256>>>(b2, out);
}

// round 10
// speedup vs baseline: 1.1638x; 1.1638x over previous
#include <cuda_runtime.h>
#include <cuda_bf16.h>

#define NN 100000
#define NE 3200000
#define DF 512
#define HID 16
#define NC 7

// gemm1: 512 rows x 16 cols x 128-k-slice per 256-thread block; thread = 2 rows x 16 cols
#define GROWS 512
#define GKS   128          // k-slice per block (split-K = 4)
#define GKC   16           // k per staged chunk
#define GXST  17           // padded xs row stride (floats)

// ---------------- scratch (no allocations allowed) ----------------
__device__ float g_deg[NN];
__device__ float g_dinv[NN];
__device__ __align__(16) float g_h1[NN * HID];   // h1s = dinv * (x @ W1), red-accumulated
__device__ __align__(16) float g_m1[NN * HID];   // sum of h1s[src] over in-edges
__device__ __align__(16) float g_t2[NN * 8];     // t2s = dinv * (h2 @ W2), padded to 8
__device__ __align__(16) float g_m2[NN * 8];     // sum of t2s[src], padded

// 128-bit global float reduction (sm_90+)
__device__ __forceinline__ void red_add_v4(float* p, float4 v) {
    asm volatile(
        "{\n\t"
        ".reg .u64 pg;\n\t"
        "cvta.to.global.u64 pg, %0;\n\t"
        "red.global.add.v4.f32 [pg], {%1,%2,%3,%4};\n\t"
        "}"
        :: "l"(p), "f"(v.x), "f"(v.y), "f"(v.z), "f"(v.w)
        : "memory");
}

__device__ __forceinline__ void ffma2(unsigned long long& acc,
                                      unsigned long long a, unsigned long long b) {
    asm("fma.rn.f32x2 %0, %1, %2, %0;" : "+l"(acc) : "l"(a), "l"(b));
}

// ---------------- K0: init accumulators (float4 stores) ----------------
__global__ void k_init() {
    int i = blockIdx.x * blockDim.x + threadIdx.x;
    float4 z = make_float4(0.f, 0.f, 0.f, 0.f);
    if (i < NN) g_deg[i] = 1.0f;          // self-loop contributes 1 to degree
    if (i < NN * 4) { ((float4*)g_m1)[i] = z; ((float4*)g_h1)[i] = z; }
    if (i < NN * 2) ((float4*)g_m2)[i] = z;
}

// ---------------- K1: in-degree ----------------
__global__ void k_deg(const int* __restrict__ ei) {
    int e = blockIdx.x * blockDim.x + threadIdx.x;
    if (e < NE) atomicAdd(&g_deg[ei[NE + e]], 1.0f);
}

// ---------------- K2: dinv ----------------
__global__ void k_dinv() {
    int i = blockIdx.x * blockDim.x + threadIdx.x;
    if (i < NN) g_dinv[i] = rsqrtf(g_deg[i]);   // deg >= 1 always
}

// ---------------- K3: h1s += dinv * (x @ W1)  (R5 config, proven 76us) -------
__global__ __launch_bounds__(256) void k_gemm1(const float* __restrict__ x,
                                               const float* __restrict__ W1) {
    __shared__ float xs[GROWS * GXST];              // 34.8 KB
    __shared__ __align__(8) float2 Wp[GKS][8];      // 8 KB (col pairs)

    int t = threadIdx.x;
    int rb = blockIdx.x >> 2;
    int ks = (blockIdx.x & 3) * GKS;
    int row0 = rb * GROWS;

    // stage W slice as col-pairs (coalesced float2 loads)
    const float2* W2p = (const float2*)W1;
    #pragma unroll
    for (int i = t; i < GKS * 8; i += 256) {
        int k = i >> 3, c = i & 7;
        Wp[k][c] = W2p[(ks + k) * 8 + c];
    }

    unsigned long long acc[2][8];
    #pragma unroll
    for (int p = 0; p < 2; p++)
        #pragma unroll
        for (int c = 0; c < 8; c++) acc[p][c] = 0ull;

    for (int ch = 0; ch < GKS / GKC; ch++) {
        __syncthreads();
        // stage x chunk: 512 rows x 16 k, row-major padded
        #pragma unroll
        for (int i = 0; i < 8; i++) {
            int lin = t + 256 * i;
            int row = lin >> 2, j = lin & 3;
            int grow = row0 + row;
            float4 v = make_float4(0.f, 0.f, 0.f, 0.f);
            if (grow < NN) v = *(const float4*)&x[grow * DF + ks + ch * GKC + j * 4];
            float* p = &xs[row * GXST + j * 4];
            p[0] = v.x; p[1] = v.y; p[2] = v.z; p[3] = v.w;
        }
        __syncthreads();
        #pragma unroll
        for (int kk = 0; kk < GKC; kk++) {
            int kL = ch * GKC + kk;
            float xa = xs[t * GXST + kk];
            float xb = xs[(t + 256) * GXST + kk];
            unsigned long long xad, xbd;
            asm("mov.b64 %0, {%1,%1};" : "=l"(xad) : "f"(xa));
            asm("mov.b64 %0, {%1,%1};" : "=l"(xbd) : "f"(xb));
            #pragma unroll
            for (int c = 0; c < 8; c++) {
                unsigned long long w = *(const unsigned long long*)&Wp[kL][c];
                ffma2(acc[0][c], xad, w);
                ffma2(acc[1][c], xbd, w);
            }
        }
    }

    #pragma unroll
    for (int p = 0; p < 2; p++) {
        int rr = row0 + t + p * 256;
        if (rr < NN) {
            float dv = g_dinv[rr];
            float f[16];
            #pragma unroll
            for (int c = 0; c < 8; c++) {
                asm("mov.b64 {%0,%1}, %2;" : "=f"(f[2 * c]), "=f"(f[2 * c + 1]) : "l"(acc[p][c]));
                f[2 * c] *= dv; f[2 * c + 1] *= dv;
            }
            red_add_v4(&g_h1[rr * HID + 0],  make_float4(f[0],  f[1],  f[2],  f[3]));
            red_add_v4(&g_h1[rr * HID + 4],  make_float4(f[4],  f[5],  f[6],  f[7]));
            red_add_v4(&g_h1[rr * HID + 8],  make_float4(f[8],  f[9],  f[10], f[11]));
            red_add_v4(&g_h1[rr * HID + 12], make_float4(f[12], f[13], f[14], f[15]));
        }
    }
}

// ---------------- K4: layer-1 scatter (4 threads/edge, unweighted) ----------
__global__ void k_scat1(const int* __restrict__ ei) {
    int t = blockIdx.x * blockDim.x + threadIdx.x;
    int e = t >> 2, sub = t & 3;
    if (e >= NE) return;
    int src = ei[e];
    int dst = ei[NE + e];
    float4 h = ((const float4*)g_h1)[src * 4 + sub];
    red_add_v4(&g_m1[dst * HID + sub * 4], h);
}

// ---------------- K5: h2 = relu(dinv*(m1 + h1s) + b1); t2s = dinv*(h2 @ W2) -
__global__ void k_layer2(const float* __restrict__ b1, const float* __restrict__ W2) {
    __shared__ float W2s[HID][8];
    __shared__ float b1s[HID];
    int t = threadIdx.x;
    if (t < HID * NC) W2s[t / NC][t % NC] = W2[t];
    if (t < HID) { W2s[t][7] = 0.0f; b1s[t] = b1[t]; }
    __syncthreads();

    int n = blockIdx.x * blockDim.x + t;
    if (n >= NN) return;
    float dv = g_dinv[n];

    float h[HID];
    #pragma unroll
    for (int j = 0; j < 4; j++) {
        float4 mv = ((const float4*)g_m1)[n * 4 + j];
        float4 hv = ((const float4*)g_h1)[n * 4 + j];
        h[4 * j + 0] = fmaxf(dv * (mv.x + hv.x) + b1s[4 * j + 0], 0.f);
        h[4 * j + 1] = fmaxf(dv * (mv.y + hv.y) + b1s[4 * j + 1], 0.f);
        h[4 * j + 2] = fmaxf(dv * (mv.z + hv.z) + b1s[4 * j + 2], 0.f);
        h[4 * j + 3] = fmaxf(dv * (mv.w + hv.w) + b1s[4 * j + 3], 0.f);
    }

    float o[8];
    #pragma unroll
    for (int c = 0; c < 8; c++) o[c] = 0.f;
    #pragma unroll
    for (int k = 0; k < HID; k++) {
        #pragma unroll
        for (int c = 0; c < 8; c++)
            o[c] += h[k] * W2s[k][c];    // col 7 stays 0
    }
    #pragma unroll
    for (int c = 0; c < 8; c++) o[c] *= dv;   // pre-scale by own dinv
    ((float4*)g_t2)[n * 2 + 0] = make_float4(o[0], o[1], o[2], o[3]);
    ((float4*)g_t2)[n * 2 + 1] = make_float4(o[4], o[5], o[6], o[7]);
}

// ---------------- K6: layer-2 scatter (2 threads/edge, unweighted) ----------
__global__ void k_scat2(const int* __restrict__ ei) {
    int t = blockIdx.x * blockDim.x + threadIdx.x;
    int e = t >> 1, sub = t & 1;
    if (e >= NE) return;
    int src = ei[e];
    int dst = ei[NE + e];
    float4 v = ((const float4*)g_t2)[src * 2 + sub];
    red_add_v4(&g_m2[dst * 8 + sub * 4], v);
}

// ---------------- K7: finalize: logits = dinv*(m2 + t2s) + b2; log_softmax --
__global__ void k_final(const float* __restrict__ b2, float* __restrict__ out) {
    int n = blockIdx.x * blockDim.x + threadIdx.x;
    if (n >= NN) return;
    float dv = g_dinv[n];

    float4 m0 = ((const float4*)g_m2)[n * 2 + 0];
    float4 m1v = ((const float4*)g_m2)[n * 2 + 1];
    float4 t0 = ((const float4*)g_t2)[n * 2 + 0];
    float4 t1 = ((const float4*)g_t2)[n * 2 + 1];

    float l[NC];
    l[0] = dv * (m0.x + t0.x) + b2[0];
    l[1] = dv * (m0.y + t0.y) + b2[1];
    l[2] = dv * (m0.z + t0.z) + b2[2];
    l[3] = dv * (m0.w + t0.w) + b2[3];
    l[4] = dv * (m1v.x + t1.x) + b2[4];
    l[5] = dv * (m1v.y + t1.y) + b2[5];
    l[6] = dv * (m1v.z + t1.z) + b2[6];

    float mx = l[0];
    #pragma unroll
    for (int c = 1; c < NC; c++) mx = fmaxf(mx, l[c]);
    float s = 0.f;
    #pragma unroll
    for (int c = 0; c < NC; c++) s += expf(l[c] - mx);
    float lse = mx + logf(s);
    #pragma unroll
    for (int c = 0; c < NC; c++) out[n * NC + c] = l[c] - lse;
}

// ---------------- launch ----------------
extern "C" void kernel_launch(void* const* d_in, const int* in_sizes, int n_in,
                              void* d_out, int out_size) {
    const float* x   = (const float*)d_in[0];
    const int*   ei  = (const int*)d_in[1];
    const float* W1  = (const float*)d_in[2];
    const float* b1  = (const float*)d_in[3];
    const float* W2  = (const float*)d_in[4];
    const float* b2  = (const float*)d_in[5];
    float*       out = (float*)d_out;

    int gblocks = ((NN + GROWS - 1) / GROWS) * 4;   // 196 * 4 = 784

    k_init<<<(NN * 4 + 255) / 256, 256>>>();
    k_deg<<<(NE + 255) / 256, 256>>>(ei);
    k_dinv<<<(NN + 255) / 256, 256>>>();
    k_gemm1<<<gblocks, 256>>>(x, W1);
    k_scat1<<<(NE * 4 + 255) / 256, 256>>>(ei);
    k_layer2<<<(NN + 255) / 256, 256>>>(b1, W2);
    k_scat2<<<(NE * 2 + 255) / 256, 256>>>(ei);
    k_final<<<(NN + 255) / 256, 256>>>(b2, out);
}